// round 4
// baseline (speedup 1.0000x reference)
#include <cuda_runtime.h>

// adapt_smoothing: out[b,s,f] = sum_{l=0..24} w[l] * x[b, max(s+l-24,0), f]
// x: [B=32, S=4096, F=512] fp32, w: [K=25] fp32.
//
// v3: linear 49-slot register window instead of a ring. Per 25-step chunk:
//   1) 25 independent LDG.64 into fresh regs win[24..48]  (MLP=25, no WAR)
//   2) 25 outputs: out[p] = sum_l pw[l] (*) win[p+l]       (static indices)
//   3) shift win[0..23] = win[25..48]                      (ALU movs, cheap)
// float2 lanes + packed fma.rn.f32x2 throughout. ~160 regs -> 3 CTAs/SM,
// but 6.4KB of loads in flight per warp hides DRAM latency without occupancy.

#define B_DIM 32
#define S_DIM 4096
#define F_DIM 512
#define K_DIM 25
#define P_DIM (F_DIM / 2)   // 256 float2 columns
#define S_TILE 200          // multiple of 25; grid=1344 = 3.03 waves @ 3 CTA/SM
#define BLOCK_P 128
#define W_DIM (2 * K_DIM - 1)   // 49-slot window

typedef unsigned long long u64;

__device__ __forceinline__ u64 pack2(float v) {
    union { float f[2]; u64 u; } c;
    c.f[0] = v; c.f[1] = v;
    return c.u;
}
__device__ __forceinline__ u64 fma2(u64 a, u64 b, u64 c) {
    u64 d; asm("fma.rn.f32x2 %0, %1, %2, %3;" : "=l"(d) : "l"(a), "l"(b), "l"(c)); return d;
}
__device__ __forceinline__ u64 add2(u64 a, u64 b) {
    u64 d; asm("add.rn.f32x2 %0, %1, %2;" : "=l"(d) : "l"(a), "l"(b)); return d;
}

__global__ __launch_bounds__(BLOCK_P, 3) void adapt_smoothing_kernel(
    const float* __restrict__ x,
    const float* __restrict__ w,
    float* __restrict__ out)
{
    const int fp = blockIdx.x * BLOCK_P + threadIdx.x;   // float2 column, 0..255
    const int s0 = blockIdx.y * S_TILE;                  // multiple of 25
    const int b  = blockIdx.z;

    const u64* __restrict__ xv = (const u64*)x;
    u64* __restrict__ ov = (u64*)out;
    const int boff = b * (S_DIM * P_DIM) + fp;           // max ~33.5M, fits int

    // Weights -> packed 64-bit broadcast registers.
    u64 pw[K_DIM];
#pragma unroll
    for (int l = 0; l < K_DIM; ++l) pw[l] = pack2(__ldg(&w[l]));

    // Window invariant at chunk start (chunk base T = s0 + j):
    //   win[q] = x[b, T-24+q, :] for q = 0..23   (clamped at t<0)
    // Preload the 24 history values.
    u64 win[W_DIM];
#pragma unroll
    for (int q = 0; q < K_DIM - 1; ++q) {
        int t = s0 - (K_DIM - 1) + q;
        if (t < 0) t = 0;
        win[q] = __ldg(&xv[boff + t * P_DIM]);
    }

    for (int j = 0; j < S_TILE; j += K_DIM) {
        const int tbase = s0 + j;

        // --- 1) Front-batched loads: 25 independent LDG.64 into fresh regs ---
#pragma unroll
        for (int q = 0; q < K_DIM; ++q) {
            const int t = tbase + q;
            u64 v = 0ULL;
            if (t < S_DIM) v = __ldg(&xv[boff + t * P_DIM]);
            win[(K_DIM - 1) + q] = v;
        }

        // --- 2) 25 outputs from the static window ---
#pragma unroll
        for (int p = 0; p < K_DIM; ++p) {
            u64 a0 = 0ULL, a1 = 0ULL, a2 = 0ULL, a3 = 0ULL;
#pragma unroll
            for (int l = 0; l < K_DIM; l += 4) {
                a0 = fma2(pw[l], win[p + l], a0);
                if (l + 1 < K_DIM) a1 = fma2(pw[l + 1], win[p + l + 1], a1);
                if (l + 2 < K_DIM) a2 = fma2(pw[l + 2], win[p + l + 2], a2);
                if (l + 3 < K_DIM) a3 = fma2(pw[l + 3], win[p + l + 3], a3);
            }
            const u64 acc = add2(add2(a0, a1), add2(a2, a3));

            const int t = tbase + p;
            if (t < S_DIM) ov[boff + t * P_DIM] = acc;
        }

        // --- 3) Shift history: win[0..23] = win[25..48] ---
#pragma unroll
        for (int q = 0; q < K_DIM - 1; ++q) win[q] = win[q + K_DIM];
    }
}

extern "C" void kernel_launch(void* const* d_in, const int* in_sizes, int n_in,
                              void* d_out, int out_size)
{
    const float* x = (const float*)d_in[0];
    const float* w = (const float*)d_in[1];
    float* out = (float*)d_out;

    const int n_chunks = (S_DIM + S_TILE - 1) / S_TILE;  // 21
    dim3 grid(P_DIM / BLOCK_P, n_chunks, B_DIM);         // (2, 21, 32)
    dim3 block(BLOCK_P);
    adapt_smoothing_kernel<<<grid, block>>>(x, w, out);
}

// round 6
// speedup vs baseline: 1.2294x; 1.2294x over previous
#include <cuda_runtime.h>

// adapt_smoothing: out[b,s,f] = sum_{l=0..24} w[l] * x[b, max(s+l-24,0), f]
// x: [B=32, S=4096, F=512] fp32, w: [K=25] fp32.
//
// v5 = v4 + tail-drain fix. cp.async staging FIFO: each thread streams its
// float2 column through a private smem ring (8B/thread/row, 30 rows in
// flight). Consumer: LDS.64 -> 25-slot register ring (statically indexed),
// 13 packed fma.rn.f32x2 per output pair, STG.64. No __syncthreads (producer
// and consumer use identical per-thread byte mapping).
// FIX: in the drain phase, commit EMPTY cp.async groups so the
// "issued == bat + DEPTH" invariant holds and wait_group(DEPTH-1) always
// proves batch `bat` is complete (v4 under-drained the last 30 rows/chunk).

#define B_DIM  32
#define S_DIM  4096
#define F_DIM  512
#define K_DIM  25
#define P_DIM  (F_DIM / 2)    // 256 u64 columns total
#define HALF_P 128            // u64 columns per block
#define S_TILE 200            // outputs per chunk (multiple of 25)
#define ROWS   225            // 25 history rows + 200 output rows
#define BATCH  5
#define NBATCH (ROWS / BATCH) // 45
#define NSB    8              // smem ring slots (in batches)
#define DEPTH  6              // batches in flight (30 rows)

typedef unsigned long long u64;

__device__ __forceinline__ u64 pack2(float v) {
    union { float f[2]; u64 u; } c;
    c.f[0] = v; c.f[1] = v;
    return c.u;
}
__device__ __forceinline__ u64 fma2(u64 a, u64 b, u64 c) {
    u64 d; asm("fma.rn.f32x2 %0, %1, %2, %3;" : "=l"(d) : "l"(a), "l"(b), "l"(c)); return d;
}
__device__ __forceinline__ u64 add2(u64 a, u64 b) {
    u64 d; asm("add.rn.f32x2 %0, %1, %2;" : "=l"(d) : "l"(a), "l"(b)); return d;
}

__global__ __launch_bounds__(128, 3) void adapt_smoothing_kernel(
    const float* __restrict__ x,
    const float* __restrict__ w,
    float* __restrict__ out)
{
    __shared__ u64 stage[NSB * BATCH * HALF_P];   // 40 KB

    const int tid = threadIdx.x;
    const int fp  = blockIdx.x * HALF_P + tid;    // u64 column, 0..255
    const int s0  = blockIdx.y * S_TILE;          // multiple of 25
    const int bz  = blockIdx.z;

    const u64* __restrict__ xv = (const u64*)x;
    u64* __restrict__ ov = (u64*)out;
    const int boff = bz * (S_DIM * P_DIM) + fp;   // max ~33.5M, fits int

    // Packed broadcast weights (both f32 halves = w[l]).
    u64 pw[K_DIM];
#pragma unroll
    for (int l = 0; l < K_DIM; ++l) pw[l] = pack2(__ldg(&w[l]));

    // Producer: stage batch `bat` (5 rows, 8B per thread per row), or commit
    // an EMPTY group when bat >= NBATCH (keeps group-count arithmetic exact
    // through the drain phase -- empty groups are legal and complete at once).
    auto issue_batch = [&](int bat) {
        if (bat < NBATCH) {
            const int base_r = bat * BATCH;
            u64* dst = &stage[(bat & (NSB - 1)) * (BATCH * HALF_P) + tid];
#pragma unroll
            for (int rr = 0; rr < BATCH; ++rr) {
                int t = s0 - K_DIM + base_r + rr;               // row timestep
                t = t < 0 ? 0 : (t >= S_DIM ? S_DIM - 1 : t);   // edge clamp
                const u64* src = &xv[boff + t * P_DIM];
                unsigned saddr = (unsigned)__cvta_generic_to_shared(dst + rr * HALF_P);
                asm volatile("cp.async.ca.shared.global [%0], [%1], 8;\n"
                             :: "r"(saddr), "l"(src));
            }
        }
        asm volatile("cp.async.commit_group;\n");
    };

    // Prologue: DEPTH batches in flight.
#pragma unroll
    for (int bq = 0; bq < DEPTH; ++bq) issue_batch(bq);

    u64 ring[K_DIM];   // ring[t % 25] = x[b, t, col]

    for (int bb = 0; bb < NBATCH / 5; ++bb) {     // 9 outer iterations
#pragma unroll
        for (int sub = 0; sub < 5; ++sub) {       // 5 batches => 25 rows, static
            const int bat = bb * 5 + sub;

            // Invariant: groups committed == bat + DEPTH. wait_group(DEPTH-1)
            // therefore proves groups 0..bat are complete.
            asm volatile("cp.async.wait_group %0;\n" :: "n"(DEPTH - 1));

            // Refill (or empty-commit in the drain phase).
            issue_batch(bat + DEPTH);

            const u64* src = &stage[(bat & (NSB - 1)) * (BATCH * HALF_P) + tid];
#pragma unroll
            for (int rr = 0; rr < BATCH; ++rr) {
                const int p = sub * BATCH + rr;   // static 0..24 == r % 25
                const int r = bat * BATCH + rr;
                const int t = s0 - K_DIM + r;

                ring[p] = src[rr * HALF_P];       // LDS.64 (own bytes)

                if (r >= K_DIM && t < S_DIM) {
                    // out[t] = sum_l pw[l] (*) ring[(p+1+l) % 25]
                    u64 a0 = 0ULL, a1 = 0ULL, a2 = 0ULL, a3 = 0ULL;
#pragma unroll
                    for (int l = 0; l < K_DIM; l += 4) {
                        a0 = fma2(pw[l], ring[(p + 1 + l) % K_DIM], a0);
                        if (l + 1 < K_DIM) a1 = fma2(pw[l + 1], ring[(p + 2 + l) % K_DIM], a1);
                        if (l + 2 < K_DIM) a2 = fma2(pw[l + 2], ring[(p + 3 + l) % K_DIM], a2);
                        if (l + 3 < K_DIM) a3 = fma2(pw[l + 3], ring[(p + 4 + l) % K_DIM], a3);
                    }
                    ov[boff + t * P_DIM] = add2(add2(a0, a1), add2(a2, a3));
                }
            }
        }
    }
}

extern "C" void kernel_launch(void* const* d_in, const int* in_sizes, int n_in,
                              void* d_out, int out_size)
{
    const float* x = (const float*)d_in[0];
    const float* w = (const float*)d_in[1];
    float* out = (float*)d_out;

    const int n_chunks = (S_DIM + S_TILE - 1) / S_TILE;   // 21
    dim3 grid(P_DIM / HALF_P, n_chunks, B_DIM);           // (2, 21, 32) = 1344
    dim3 block(HALF_P);
    adapt_smoothing_kernel<<<grid, block>>>(x, w, out);
}